// round 5
// baseline (speedup 1.0000x reference)
#include <cuda_runtime.h>
#include <cuda_bf16.h>
#include <math.h>

// ---------------- problem constants ----------------
#define BB   8
#define NN   3136        // 56*56
#define DM   512
#define NH   4
#define DK   128         // head_qk
#define DV   256         // head_v
#define CH   64          // chunk
#define NC   49          // chunks per sequence
#define MTOT (BB*NN)     // 25088
#define NSEQ 64          // 2 dir * 8 b * 4 h

// padded smem strides
#define PDK 132
#define PDV 260
#define PCH 68

// ---------------- scratch (device globals; no allocation) ----------------
__device__ float g_xs  [MTOT * DM];          // conv+silu output
__device__ float g_qkv [MTOT * 2048];        // q(512) k(512) v(1024)
__device__ float g_t16 [MTOT * 16];          // low-rank intermediate
__device__ float g_gk  [MTOT * 1024];        // gates (f 512 | b 512), log-sig/16
__device__ float g_g   [MTOT * 1024];        // output gate pre-silu
__device__ float g_qe  [(size_t)NSEQ * NN * DK];    // decayed scaled q per seq
__device__ float g_od  [2][(size_t)32 * NN * DV];   // o_fwd / o_bwd (orig positions)
__device__ float g_S   [(size_t)NSEQ * NC * DK * DV]; // local states -> prefix states
__device__ float g_dec [NSEQ * NC * DK];     // per-chunk decay exp(btot)
__device__ float g_ob  [MTOT * 1024];        // gated combined output

// ---------------- depthwise conv 3x3 + SiLU ----------------
__global__ void __launch_bounds__(256) conv_silu_kernel(
    const float* __restrict__ x, const float* __restrict__ w)
{
    int idx = blockIdx.x * 256 + threadIdx.x;       // over MTOT*512
    int c = idx & 511;
    int m = idx >> 9;
    int b = m / NN;
    int n = m - b * NN;
    int h = n / 56, ww = n - h * 56;
    float acc = 0.f;
    #pragma unroll
    for (int dh = -1; dh <= 1; dh++) {
        int hh = h + dh;
        if ((unsigned)hh >= 56u) continue;
        #pragma unroll
        for (int dw = -1; dw <= 1; dw++) {
            int w2 = ww + dw;
            if ((unsigned)w2 >= 56u) continue;
            acc += x[(((size_t)b * NN + hh * 56 + w2) << 9) + c] * w[c * 9 + (dh + 1) * 3 + (dw + 1)];
        }
    }
    g_xs[idx] = acc / (1.f + expf(-acc));
}

// ---------------- tiled GEMM: C[M,Nc] = A[M,K] * B[Nc,K]^T (+bias) ----------------
// 128x128 tile, BK=8, 256 threads, 8x8 microtile, register prefetch of next k-tile.
__global__ void __launch_bounds__(256) gemm_nt_kernel(
    const float* __restrict__ A, const float* __restrict__ Bm,
    const float* __restrict__ bias, float* __restrict__ C, int K, int Nc)
{
    __shared__ float As[8][128];
    __shared__ float Bs[8][128];
    const int tid = threadIdx.x;
    const int m0 = blockIdx.y * 128;
    const int n0 = blockIdx.x * 128;
    const int tx = tid & 15, ty = tid >> 4;

    // load mapping: each thread loads one float4 of A and one of B per k-tile
    const int lr = tid >> 1;             // 0..127 row within tile
    const int lk = (tid & 1) * 4;        // 0 or 4 within BK=8
    const float* Ap = A + (size_t)(m0 + lr) * K + lk;
    const float* Bp = Bm + (size_t)(n0 + lr) * K + lk;

    float acc[8][8] = {};

    float4 av = *(const float4*)(Ap);
    float4 bv = *(const float4*)(Bp);

    for (int k0 = 0; k0 < K; k0 += 8) {
        As[lk + 0][lr] = av.x; As[lk + 1][lr] = av.y; As[lk + 2][lr] = av.z; As[lk + 3][lr] = av.w;
        Bs[lk + 0][lr] = bv.x; Bs[lk + 1][lr] = bv.y; Bs[lk + 2][lr] = bv.z; Bs[lk + 3][lr] = bv.w;
        __syncthreads();
        if (k0 + 8 < K) {                 // prefetch next tile while computing this one
            av = *(const float4*)(Ap + k0 + 8);
            bv = *(const float4*)(Bp + k0 + 8);
        }
        #pragma unroll
        for (int kk = 0; kk < 8; kk++) {
            float a[8], bb[8];
            *(float4*)&a[0]  = *(const float4*)&As[kk][ty * 8 + 0];
            *(float4*)&a[4]  = *(const float4*)&As[kk][ty * 8 + 4];
            *(float4*)&bb[0] = *(const float4*)&Bs[kk][tx * 8 + 0];
            *(float4*)&bb[4] = *(const float4*)&Bs[kk][tx * 8 + 4];
            #pragma unroll
            for (int i = 0; i < 8; i++)
                #pragma unroll
                for (int j = 0; j < 8; j++) acc[i][j] += a[i] * bb[j];
        }
        __syncthreads();
    }
    // epilogue: bias add (if any) then vectorized 128-bit stores
    if (bias) {
        float bvreg[8];
        *(float4*)&bvreg[0] = *(const float4*)&bias[n0 + tx * 8 + 0];
        *(float4*)&bvreg[4] = *(const float4*)&bias[n0 + tx * 8 + 4];
        #pragma unroll
        for (int i = 0; i < 8; i++)
            #pragma unroll
            for (int j = 0; j < 8; j++) acc[i][j] += bvreg[j];
    }
    #pragma unroll
    for (int i = 0; i < 8; i++) {
        int m = m0 + ty * 8 + i;
        float* crow = C + (size_t)m * Nc + n0 + tx * 8;
        *(float4*)(crow + 0) = *(const float4*)&acc[i][0];
        *(float4*)(crow + 4) = *(const float4*)&acc[i][4];
    }
}

// ---------------- low-rank gate, stage 1: t16 = xs @ gk_w1^T ----------------
__global__ void __launch_bounds__(256) lowrank1_kernel(const float* __restrict__ w1)
{
    __shared__ float xs_s[16][512];
    int m0 = blockIdx.x * 16;
    for (int e = threadIdx.x; e < 16 * 512; e += 256)
        xs_s[e >> 9][e & 511] = g_xs[(size_t)(m0 + (e >> 9)) * 512 + (e & 511)];
    __syncthreads();
    int r = threadIdx.x & 15, mi = threadIdx.x >> 4;
    float acc = 0.f;
    for (int c = 0; c < 512; c++) acc += xs_s[mi][c] * w1[r * 512 + c];
    g_t16[(m0 + mi) * 16 + r] = acc;
}

// ---------------- gate stage 2: gk = logsigmoid(t16 @ w2^T + b2)/16 ----------------
__global__ void __launch_bounds__(256) gk_act_kernel(
    const float* __restrict__ w2, const float* __restrict__ b2)
{
    __shared__ float t[16];
    int m = blockIdx.x;
    if (threadIdx.x < 16) t[threadIdx.x] = g_t16[m * 16 + threadIdx.x];
    __syncthreads();
    for (int o = threadIdx.x; o < 1024; o += 256) {
        float acc = b2[o];
        #pragma unroll
        for (int r = 0; r < 16; r++) acc += t[r] * w2[o * 16 + r];
        float ls = fminf(acc, 0.f) - log1pf(expf(-fabsf(acc)));
        g_gk[(size_t)m * 1024 + o] = ls * (1.f / 16.f);
    }
}

// ---------------- GLA phase 1: per-chunk intra attention + local state ----------------
// grid: NSEQ*NC blocks; dynamic smem layout below.
#define SM1_FLOATS (3 * 64 * PDK + 64 * PDV + 64 * PCH + 128)
__global__ void __launch_bounds__(256) gla1_kernel()
{
    extern __shared__ float sm[];
    float* sB = sm;                   // [64][PDK] cumsum gates
    float* sQ = sB + 64 * PDK;        // [64][PDK] qe
    float* sK = sQ + 64 * PDK;        // [64][PDK] k*exp(-b)
    float* sV = sK + 64 * PDK;        // [64][PDV] v
    float* sA = sV + 64 * PDV;        // [64][PCH] masked scores
    float* sE = sA + 64 * PCH;        // [128] exp(btot)

    const int blk = blockIdx.x;
    const int c = blk % NC;
    const int seq = blk / NC;
    const int h = seq & 3;
    const int b = (seq >> 2) & 7;
    const int dir = seq >> 5;
    const int tid = threadIdx.x;

    // load raw gates for this chunk
    for (int e = tid; e < 64 * 128; e += 256) {
        int t = e >> 7, d = e & 127;
        int pos = dir ? (NN - 1 - (c * CH + t)) : (c * CH + t);
        sB[t * PDK + d] = g_gk[((size_t)(b * NN + pos)) * 1024 + dir * 512 + h * 128 + d];
    }
    __syncthreads();
    // inclusive cumsum over t per d; record exp(btot) and decay
    if (tid < 128) {
        float run = sB[tid];
        for (int t = 1; t < 64; t++) { run += sB[t * PDK + tid]; sB[t * PDK + tid] = run; }
        float eb = expf(run);
        sE[tid] = eb;
        g_dec[(seq * NC + c) * 128 + tid] = eb;
    }
    __syncthreads();
    // qe / ke
    const float scale = 0.08838834764831845f;   // 128^-0.5
    for (int e = tid; e < 64 * 128; e += 256) {
        int t = e >> 7, d = e & 127;
        int pos = dir ? (NN - 1 - (c * CH + t)) : (c * CH + t);
        float bb = sB[t * PDK + d];
        size_t rowq = ((size_t)(b * NN + pos)) * 2048 + h * 128 + d;
        float qe = g_qkv[rowq] * expf(bb) * scale;
        float ke = g_qkv[rowq + 512] * expf(-bb);
        sQ[t * PDK + d] = qe;
        sK[t * PDK + d] = ke;
        g_qe[((size_t)seq * NN + c * CH + t) * 128 + d] = qe;
    }
    // v
    for (int e = tid; e < 64 * 256; e += 256) {
        int t = e >> 8, j = e & 255;
        int pos = dir ? (NN - 1 - (c * CH + t)) : (c * CH + t);
        sV[t * PDV + j] = g_qkv[((size_t)(b * NN + pos)) * 2048 + 1024 + h * 256 + j];
    }
    __syncthreads();

    const int tx = tid & 15, ty = tid >> 4;
    // A[t][s] = qe_t . ke_s, causal mask
    {
        float acc[4][4] = {};
        for (int d = 0; d < 128; d++) {
            float a[4], bb[4];
            #pragma unroll
            for (int i = 0; i < 4; i++) a[i] = sQ[(ty * 4 + i) * PDK + d];
            #pragma unroll
            for (int j = 0; j < 4; j++) bb[j] = sK[(tx * 4 + j) * PDK + d];
            #pragma unroll
            for (int i = 0; i < 4; i++)
                #pragma unroll
                for (int j = 0; j < 4; j++) acc[i][j] += a[i] * bb[j];
        }
        #pragma unroll
        for (int i = 0; i < 4; i++)
            #pragma unroll
            for (int j = 0; j < 4; j++) {
                int t = ty * 4 + i, s = tx * 4 + j;
                sA[t * PCH + s] = (t >= s) ? acc[i][j] : 0.f;
            }
    }
    __syncthreads();
    // o_intra = A @ v  (4 t x 16 j per thread)
    {
        float acc[4][16] = {};
        int t0 = ty * 4, j0 = tx * 16;
        for (int s = 0; s < 64; s++) {
            float a[4];
            #pragma unroll
            for (int i = 0; i < 4; i++) a[i] = sA[(t0 + i) * PCH + s];
            #pragma unroll
            for (int j = 0; j < 16; j++) {
                float vv = sV[s * PDV + j0 + j];
                #pragma unroll
                for (int i = 0; i < 4; i++) acc[i][j] += a[i] * vv;
            }
        }
        #pragma unroll
        for (int i = 0; i < 4; i++) {
            int t = t0 + i;
            int pos = dir ? (NN - 1 - (c * CH + t)) : (c * CH + t);
            float* dst = &g_od[dir][((size_t)(b * 4 + h) * NN + pos) * 256 + j0];
            #pragma unroll
            for (int j = 0; j < 16; j++) dst[j] = acc[i][j];
        }
    }
    // local state: S_loc[d][j] = exp(btot_d) * sum_t ke[t][d] * v[t][j]
    {
        int d0 = ty * 8;
        for (int jh = 0; jh < 2; jh++) {
            int j0 = jh * 128 + tx * 8;
            float acc[8][8] = {};
            for (int s = 0; s < 64; s++) {
                float kv[8], vv[8];
                #pragma unroll
                for (int i = 0; i < 8; i++) kv[i] = sK[s * PDK + d0 + i];
                #pragma unroll
                for (int j = 0; j < 8; j++) vv[j] = sV[s * PDV + j0 + j];
                #pragma unroll
                for (int i = 0; i < 8; i++)
                    #pragma unroll
                    for (int j = 0; j < 8; j++) acc[i][j] += kv[i] * vv[j];
            }
            size_t base = ((size_t)(seq * NC + c)) * 32768;
            #pragma unroll
            for (int i = 0; i < 8; i++) {
                float eb = sE[d0 + i];
                #pragma unroll
                for (int j = 0; j < 8; j++)
                    g_S[base + (d0 + i) * 256 + j0 + j] = eb * acc[i][j];
            }
        }
    }
}

// ---------------- GLA phase 2: sequential scan over chunks (in place) ----------------
__global__ void __launch_bounds__(256) gla_scan_kernel()
{
    int g = blockIdx.x * 256 + threadIdx.x;     // < NSEQ*128*256
    int j = g & 255;
    int d = (g >> 8) & 127;
    int seq = g >> 15;
    float S = 0.f;
    size_t base = (size_t)seq * NC * 32768 + d * 256 + j;
    int dbase = seq * NC * 128 + d;
    for (int c = 0; c < NC; c++) {
        float loc = g_S[base + (size_t)c * 32768];
        float dec = g_dec[dbase + c * 128];
        g_S[base + (size_t)c * 32768] = S;       // prefix (state BEFORE chunk c)
        S = S * dec + loc;
    }
}

// ---------------- GLA phase 3: o += qe @ S_prefix ----------------
#define SM3_FLOATS (64 * PDK + 128 * PDV)
__global__ void __launch_bounds__(256) gla3_kernel()
{
    const int blk = blockIdx.x;
    const int c = blk % NC;
    if (c == 0) return;                          // prefix is zero
    const int seq = blk / NC;
    const int h = seq & 3;
    const int b = (seq >> 2) & 7;
    const int dir = seq >> 5;
    const int tid = threadIdx.x;

    extern __shared__ float sm[];
    float* sQ = sm;                  // [64][PDK]
    float* sS = sQ + 64 * PDK;       // [128][PDV]

    for (int e = tid; e < 64 * 128; e += 256) {
        int t = e >> 7, d = e & 127;
        sQ[t * PDK + d] = g_qe[((size_t)seq * NN + c * CH + t) * 128 + d];
    }
    size_t sbase = ((size_t)(seq * NC + c)) * 32768;
    for (int e = tid; e < 128 * 256; e += 256) {
        int d = e >> 8, j = e & 255;
        sS[d * PDV + j] = g_S[sbase + e];
    }
    __syncthreads();

    const int tx = tid & 15, ty = tid >> 4;
    int t0 = ty * 4, j0 = tx * 16;
    float acc[4][16] = {};
    for (int d = 0; d < 128; d++) {
        float a[4];
        #pragma unroll
        for (int i = 0; i < 4; i++) a[i] = sQ[(t0 + i) * PDK + d];
        #pragma unroll
        for (int j = 0; j < 16; j++) {
            float sv = sS[d * PDV + j0 + j];
            #pragma unroll
            for (int i = 0; i < 4; i++) acc[i][j] += a[i] * sv;
        }
    }
    #pragma unroll
    for (int i = 0; i < 4; i++) {
        int t = t0 + i;
        int pos = dir ? (NN - 1 - (c * CH + t)) : (c * CH + t);
        float* dst = &g_od[dir][((size_t)(b * 4 + h) * NN + pos) * 256 + j0];
        #pragma unroll
        for (int j = 0; j < 16; j++) dst[j] += acc[i][j];
    }
}

// ---------------- combine: rmsnorm(o_f)+rmsnorm(o_b), silu(g) gate ----------------
__global__ void __launch_bounds__(256) combine_kernel(
    const float* __restrict__ gn, const float* __restrict__ ln)
{
    int idx = blockIdx.x;            // bh*NN + n
    int n = idx % NN;
    int bh = idx / NN;
    int h = bh & 3;
    int b = bh >> 2;
    int j = threadIdx.x;

    size_t rbase = ((size_t)bh * NN + n) * 256;
    float f  = g_od[0][rbase + j];
    float bo = g_od[1][rbase + j];

    float sf = f * f, sb = bo * bo;
    #pragma unroll
    for (int o = 16; o; o >>= 1) {
        sf += __shfl_down_sync(0xFFFFFFFFu, sf, o);
        sb += __shfl_down_sync(0xFFFFFFFFu, sb, o);
    }
    __shared__ float wf[8], wb[8], tot[2];
    int lane = j & 31, wid = j >> 5;
    if (lane == 0) { wf[wid] = sf; wb[wid] = sb; }
    __syncthreads();
    if (j == 0) {
        float a = 0.f, bq = 0.f;
        #pragma unroll
        for (int i = 0; i < 8; i++) { a += wf[i]; bq += wb[i]; }
        tot[0] = a; tot[1] = bq;
    }
    __syncthreads();
    float msf = tot[0] * (1.f / 256.f);
    float msb = tot[1] * (1.f / 256.f);
    float val = f * rsqrtf(msf + 1e-5f) * gn[j] + bo * rsqrtf(msb + 1e-5f) * ln[j];
    size_t gi = ((size_t)(b * NN + n)) * 1024 + h * 256 + j;
    float gv = g_g[gi];
    g_ob[gi] = gv / (1.f + expf(-gv)) * val;
}

// ---------------- launch ----------------
extern "C" void kernel_launch(void* const* d_in, const int* in_sizes, int n_in,
                              void* d_out, int out_size)
{
    const float* x      = (const float*)d_in[0];
    const float* conv_w = (const float*)d_in[1];
    const float* qkv_w  = (const float*)d_in[2];
    const float* gk_w1  = (const float*)d_in[3];
    const float* gk_w2  = (const float*)d_in[4];
    const float* gk_b2  = (const float*)d_in[5];
    const float* g_w    = (const float*)d_in[6];
    const float* g_b    = (const float*)d_in[7];
    const float* gnorm  = (const float*)d_in[8];
    const float* lnorm  = (const float*)d_in[9];
    const float* o_w    = (const float*)d_in[10];
    float* out = (float*)d_out;

    float *p_xs, *p_qkv, *p_g, *p_ob;
    cudaGetSymbolAddress((void**)&p_xs,  g_xs);
    cudaGetSymbolAddress((void**)&p_qkv, g_qkv);
    cudaGetSymbolAddress((void**)&p_g,   g_g);
    cudaGetSymbolAddress((void**)&p_ob,  g_ob);

    cudaFuncSetAttribute(gla1_kernel, cudaFuncAttributeMaxDynamicSharedMemorySize,
                         SM1_FLOATS * (int)sizeof(float));
    cudaFuncSetAttribute(gla3_kernel, cudaFuncAttributeMaxDynamicSharedMemorySize,
                         SM3_FLOATS * (int)sizeof(float));

    // 1. conv + silu
    conv_silu_kernel<<<(MTOT * DM) / 256, 256>>>(x, conv_w);
    // 2. qkv GEMM
    gemm_nt_kernel<<<dim3(2048 / 128, MTOT / 128), 256>>>(p_xs, qkv_w, nullptr, p_qkv, 512, 2048);
    // 3. low-rank gates
    lowrank1_kernel<<<MTOT / 16, 256>>>(gk_w1);
    gk_act_kernel<<<MTOT, 256>>>(gk_w2, gk_b2);
    // 4. output-gate GEMM
    gemm_nt_kernel<<<dim3(1024 / 128, MTOT / 128), 256>>>(p_xs, g_w, g_b, p_g, 512, 1024);
    // 5. GLA
    gla1_kernel<<<NSEQ * NC, 256, SM1_FLOATS * sizeof(float)>>>();
    gla_scan_kernel<<<(NSEQ * 128 * 256) / 256, 256>>>();
    gla3_kernel<<<NSEQ * NC, 256, SM3_FLOATS * sizeof(float)>>>();
    // 6. norms + gating
    combine_kernel<<<32 * NN, 256>>>(gnorm, lnorm);
    // 7. output projection
    gemm_nt_kernel<<<dim3(512 / 128, MTOT / 128), 256>>>(p_ob, o_w, nullptr, out, 1024, 512);

    (void)in_sizes; (void)n_in; (void)out_size;
}